// round 3
// baseline (speedup 1.0000x reference)
#include <cuda_runtime.h>
#include <cuda_bf16.h>
#include <math.h>

// ---------------- problem constants ----------------
#define DIMC   192
#define HEADS  6
#define HD     32
#define NTOK   49          // window size^2
#define BW     4096        // batch*windows
#define HIDDEN 768
#define ROWS   (BW * NTOK) // 200704

// ---------------- scratch (device globals; no cudaMalloc allowed) ----------------
__device__ float g_xln[(size_t)ROWS * DIMC];    // LN1 out / LN2 out (reused)
__device__ float g_qkv[(size_t)ROWS * 3 * DIMC];
__device__ float g_att[(size_t)ROWS * DIMC];    // attention output (pre-proj)
__device__ float g_x2 [(size_t)ROWS * DIMC];    // x + attn branch
__device__ float g_hid[(size_t)ROWS * HIDDEN];  // fc1/gelu out

// ---------------- LayerNorm: one warp per row of 192 ----------------
__global__ void ln_kernel(const float* __restrict__ x,
                          const float* __restrict__ g,
                          const float* __restrict__ b,
                          float* __restrict__ y)
{
    int warp = (blockIdx.x * blockDim.x + threadIdx.x) >> 5;
    int lane = threadIdx.x & 31;
    if (warp >= ROWS) return;
    const float* xr = x + (size_t)warp * DIMC;
    float v[6];
    float s = 0.f, sq = 0.f;
#pragma unroll
    for (int i = 0; i < 6; i++) {
        v[i] = xr[lane + 32 * i];
        s += v[i];
        sq += v[i] * v[i];
    }
#pragma unroll
    for (int o = 16; o > 0; o >>= 1) {
        s  += __shfl_xor_sync(0xffffffffu, s,  o);
        sq += __shfl_xor_sync(0xffffffffu, sq, o);
    }
    float mu = s * (1.f / DIMC);
    float var = sq * (1.f / DIMC) - mu * mu;
    float rs = rsqrtf(var + 1e-5f);
    float* yr = y + (size_t)warp * DIMC;
#pragma unroll
    for (int i = 0; i < 6; i++) {
        int c = lane + 32 * i;
        yr[c] = (v[i] - mu) * rs * g[c] + b[c];
    }
}

// ---------------- tiled fp32 GEMM: C[M,N] = A[M,K]*B[K,N] (+epilogue) ----------------
// 64x64 tile, BK=16, 256 threads, 4x4 micro-tile, register-prefetch pipeline.
#define EPI_BIAS  1
#define EPI_RESID 2
#define EPI_GELU  4

__device__ __forceinline__ float gelu_exact(float v)
{
    return 0.5f * v * (1.f + erff(v * 0.70710678118654752440f));
}

template <int EPI>
__global__ __launch_bounds__(256)
void gemm_kernel(const float* __restrict__ A, const float* __restrict__ B,
                 const float* __restrict__ bias, const float* __restrict__ resid,
                 float* __restrict__ C, int M, int N, int K)
{
    __shared__ float As[16][68];   // [k][m] transposed; stride 68 keeps float4 alignment
    __shared__ float Bs[16][64];   // [k][n]

    int tid = threadIdx.x;
    int tx = tid & 15;         // n sub-tile
    int ty = tid >> 4;         // m sub-tile
    int nBase = blockIdx.x * 64;
    int mBase = blockIdx.y * 64;

    // A-load mapping: 64 rows x 16 cols, float4 per thread
    int ar  = tid >> 2;            // 0..63
    int ac4 = (tid & 3) * 4;       // 0,4,8,12
    // B-load mapping: 16 rows x 64 cols, float4 per thread
    int br  = tid >> 4;            // 0..15
    int bc4 = (tid & 15) * 4;      // 0..60

    const float* Aptr = A + (size_t)(mBase + ar) * K + ac4;
    const float* Bptr = B + (size_t)br * N + nBase + bc4;

    float acc[4][4];
#pragma unroll
    for (int i = 0; i < 4; i++)
#pragma unroll
        for (int j = 0; j < 4; j++) acc[i][j] = 0.f;

    int ktiles = K >> 4;

    // prologue: load first tile
    float4 a4 = *(const float4*)(Aptr);
    float4 b4 = *(const float4*)(Bptr);

    for (int kt = 0; kt < ktiles; kt++) {
        As[ac4 + 0][ar] = a4.x;
        As[ac4 + 1][ar] = a4.y;
        As[ac4 + 2][ar] = a4.z;
        As[ac4 + 3][ar] = a4.w;
        *(float4*)&Bs[br][bc4] = b4;
        __syncthreads();

        // prefetch next tile into registers while FMAs run
        if (kt + 1 < ktiles) {
            Aptr += 16;
            Bptr += (size_t)16 * N;
            a4 = *(const float4*)(Aptr);
            b4 = *(const float4*)(Bptr);
        }

#pragma unroll
        for (int kk = 0; kk < 16; kk++) {
            float4 av = *(const float4*)&As[kk][ty * 4];
            float4 bv = *(const float4*)&Bs[kk][tx * 4];
            float a[4] = {av.x, av.y, av.z, av.w};
            float b[4] = {bv.x, bv.y, bv.z, bv.w};
#pragma unroll
            for (int i = 0; i < 4; i++)
#pragma unroll
                for (int j = 0; j < 4; j++) acc[i][j] = fmaf(a[i], b[j], acc[i][j]);
        }
        __syncthreads();
    }

    // epilogue
    float bv[4];
    if (EPI & EPI_BIAS) {
#pragma unroll
        for (int j = 0; j < 4; j++) bv[j] = bias[nBase + tx * 4 + j];
    }
#pragma unroll
    for (int i = 0; i < 4; i++) {
        size_t row = (size_t)(mBase + ty * 4 + i);
        size_t off = row * N + nBase + tx * 4;
        float4 out;
        float o[4];
#pragma unroll
        for (int j = 0; j < 4; j++) {
            float v = acc[i][j];
            if (EPI & EPI_BIAS) v += bv[j];
            if (EPI & EPI_GELU) v = gelu_exact(v);
            o[j] = v;
        }
        if (EPI & EPI_RESID) {
            float4 r = *(const float4*)(resid + off);
            o[0] += r.x; o[1] += r.y; o[2] += r.z; o[3] += r.w;
        }
        out.x = o[0]; out.y = o[1]; out.z = o[2]; out.w = o[3];
        *(float4*)(C + off) = out;
    }
}

// ---------------- windowed attention: one block per (window, head) ----------------
__global__ __launch_bounds__(128)
void attn_kernel(const float* __restrict__ qkv,
                 const float* __restrict__ bias_table,
                 const int* __restrict__ rel_index,
                 float* __restrict__ out)
{
    __shared__ float qs[NTOK * HD];        // [t*32+d], pre-scaled
    __shared__ float ks[HD * 50];          // transposed [d*50+t]
    __shared__ float vs[NTOK * HD];        // [t*32+d]
    __shared__ float bsm[NTOK * NTOK];     // [i*49+j]
    __shared__ float sc[NTOK * 50];        // scores [i*50+j]

    int b = blockIdx.x;
    int h = blockIdx.y;
    int tid = threadIdx.x;
    const float scale = 0.17677669529663688110f; // 32^-0.5

    // load q,k,v for this (window, head)
    for (int idx = tid; idx < NTOK * HD; idx += 128) {
        int t = idx >> 5, d = idx & 31;
        size_t base = ((size_t)(b * NTOK + t)) * (3 * DIMC) + h * HD + d;
        qs[t * HD + d] = qkv[base] * scale;
        ks[d * 50 + t] = qkv[base + DIMC];
        vs[t * HD + d] = qkv[base + 2 * DIMC];
    }
    // load relative-position bias for this head
    for (int idx = tid; idx < NTOK * NTOK; idx += 128) {
        bsm[idx] = bias_table[rel_index[idx] * HEADS + h];
    }
    __syncthreads();

    // scores = q·k + bias
    for (int idx = tid; idx < NTOK * NTOK; idx += 128) {
        int i = idx / NTOK, j = idx - i * NTOK;
        float s = 0.f;
#pragma unroll
        for (int d = 0; d < HD; d++) s = fmaf(qs[i * HD + d], ks[d * 50 + j], s);
        sc[i * 50 + j] = s + bsm[idx];
    }
    __syncthreads();

    // softmax per row (one thread per row)
    if (tid < NTOK) {
        float mx = -1e30f;
#pragma unroll 7
        for (int j = 0; j < NTOK; j++) mx = fmaxf(mx, sc[tid * 50 + j]);
        float sum = 0.f;
#pragma unroll 7
        for (int j = 0; j < NTOK; j++) {
            float e = expf(sc[tid * 50 + j] - mx);
            sc[tid * 50 + j] = e;
            sum += e;
        }
        float inv = 1.f / sum;
#pragma unroll 7
        for (int j = 0; j < NTOK; j++) sc[tid * 50 + j] *= inv;
    }
    __syncthreads();

    // out[t,d] = sum_j p[t,j] * v[j,d]   -> write (B_, n, C) layout
    for (int idx = tid; idx < NTOK * HD; idx += 128) {
        int t = idx >> 5, d = idx & 31;
        float s = 0.f;
#pragma unroll 7
        for (int j = 0; j < NTOK; j++) s = fmaf(sc[t * 50 + j], vs[j * HD + d], s);
        out[((size_t)(b * NTOK + t)) * DIMC + h * HD + d] = s;
    }
}

// ---------------- launch ----------------
extern "C" void kernel_launch(void* const* d_in, const int* in_sizes, int n_in,
                              void* d_out, int out_size)
{
    const float* x       = (const float*)d_in[0];
    const float* ln1_g   = (const float*)d_in[1];
    const float* ln1_b   = (const float*)d_in[2];
    const float* qkv_w   = (const float*)d_in[3];
    const float* proj_w  = (const float*)d_in[4];
    const float* proj_b  = (const float*)d_in[5];
    const float* btab    = (const float*)d_in[6];
    const float* ln2_g   = (const float*)d_in[7];
    const float* ln2_b   = (const float*)d_in[8];
    const float* fc1_w   = (const float*)d_in[9];
    const float* fc1_b   = (const float*)d_in[10];
    const float* fc2_w   = (const float*)d_in[11];
    const float* fc2_b   = (const float*)d_in[12];
    const int*   relidx  = (const int*)d_in[13];
    float* out = (float*)d_out;

    float *xln, *qkv, *att, *x2, *hid;
    cudaGetSymbolAddress((void**)&xln, g_xln);
    cudaGetSymbolAddress((void**)&qkv, g_qkv);
    cudaGetSymbolAddress((void**)&att, g_att);
    cudaGetSymbolAddress((void**)&x2,  g_x2);
    cudaGetSymbolAddress((void**)&hid, g_hid);

    // 1) LN1
    ln_kernel<<<ROWS / 8, 256>>>(x, ln1_g, ln1_b, xln);
    // 2) QKV gemm: (ROWS,192)x(192,576)
    gemm_kernel<0><<<dim3(3 * DIMC / 64, ROWS / 64), 256>>>(xln, qkv_w, nullptr, nullptr, qkv, ROWS, 3 * DIMC, DIMC);
    // 3) attention
    attn_kernel<<<dim3(BW, HEADS), 128>>>(qkv, btab, relidx, att);
    // 4) proj + bias + residual(x) -> x2
    gemm_kernel<EPI_BIAS | EPI_RESID><<<dim3(DIMC / 64, ROWS / 64), 256>>>(att, proj_w, proj_b, x, x2, ROWS, DIMC, DIMC);
    // 5) LN2 -> xln (reuse)
    ln_kernel<<<ROWS / 8, 256>>>(x2, ln2_g, ln2_b, xln);
    // 6) fc1 + bias + gelu
    gemm_kernel<EPI_BIAS | EPI_GELU><<<dim3(HIDDEN / 64, ROWS / 64), 256>>>(xln, fc1_w, fc1_b, nullptr, hid, ROWS, HIDDEN, DIMC);
    // 7) fc2 + bias + residual(x2) -> out
    gemm_kernel<EPI_BIAS | EPI_RESID><<<dim3(DIMC / 64, ROWS / 64), 256>>>(hid, fc2_w, fc2_b, x2, out, ROWS, DIMC, HIDDEN);
}

// round 4
// speedup vs baseline: 1.2310x; 1.2310x over previous
#include <cuda_runtime.h>
#include <cuda_bf16.h>
#include <math.h>

// ---------------- problem constants ----------------
#define DIMC   192
#define HEADS  6
#define HD     32
#define NTOK   49          // window size^2
#define BW     4096        // batch*windows
#define HIDDEN 768
#define ROWS   (BW * NTOK) // 200704

// ---------------- scratch (device globals; no cudaMalloc allowed) ----------------
__device__ float g_xln[(size_t)ROWS * DIMC];    // LN1 out / LN2 out (reused)
__device__ float g_qkv[(size_t)ROWS * 3 * DIMC];
__device__ float g_att[(size_t)ROWS * DIMC];    // attention output (pre-proj)
__device__ float g_x2 [(size_t)ROWS * DIMC];    // x + attn branch
__device__ float g_hid[(size_t)ROWS * HIDDEN];  // fc1/gelu out

// ---------------- LayerNorm: one warp per row of 192 ----------------
__global__ void ln_kernel(const float* __restrict__ x,
                          const float* __restrict__ g,
                          const float* __restrict__ b,
                          float* __restrict__ y)
{
    int warp = (blockIdx.x * blockDim.x + threadIdx.x) >> 5;
    int lane = threadIdx.x & 31;
    if (warp >= ROWS) return;
    const float* xr = x + (size_t)warp * DIMC;
    float v[6];
    float s = 0.f, sq = 0.f;
#pragma unroll
    for (int i = 0; i < 6; i++) {
        v[i] = xr[lane + 32 * i];
        s += v[i];
        sq += v[i] * v[i];
    }
#pragma unroll
    for (int o = 16; o > 0; o >>= 1) {
        s  += __shfl_xor_sync(0xffffffffu, s,  o);
        sq += __shfl_xor_sync(0xffffffffu, sq, o);
    }
    float mu = s * (1.f / DIMC);
    float var = sq * (1.f / DIMC) - mu * mu;
    float rs = rsqrtf(var + 1e-5f);
    float* yr = y + (size_t)warp * DIMC;
#pragma unroll
    for (int i = 0; i < 6; i++) {
        int c = lane + 32 * i;
        yr[c] = (v[i] - mu) * rs * g[c] + b[c];
    }
}

// ---------------- tiled fp32 GEMM: C[M,N] = A[M,K]*B[K,N] (+epilogue) ----------------
// 256x64 block tile, BK=16, 256 threads, 16x4 micro-tile, register prefetch.
// Shared-byte per FMA = 1.25 (was 2.0 with 4x4), lifting the smem-crossbar bound.
#define EPI_BIAS  1
#define EPI_RESID 2
#define EPI_GELU  4

#define BM 256
#define BN 64
#define BK 16
#define AS_STRIDE 260   // float4-aligned (260*4B % 16 == 0); 2-way store conflict only

__device__ __forceinline__ float gelu_exact(float v)
{
    return 0.5f * v * (1.f + erff(v * 0.70710678118654752440f));
}

template <int EPI>
__global__ __launch_bounds__(256, 2)
void gemm_kernel(const float* __restrict__ A, const float* __restrict__ B,
                 const float* __restrict__ bias, const float* __restrict__ resid,
                 float* __restrict__ C, int M, int N, int K)
{
    __shared__ float As[BK][AS_STRIDE];   // [k][m] transposed
    __shared__ float Bs[BK][BN];          // [k][n]

    int tid = threadIdx.x;
    int tx = tid & 15;         // n sub-tile (4 cols)
    int ty = tid >> 4;         // m sub-tile (16 rows)
    int nBase = blockIdx.x * BN;
    int mBase = blockIdx.y * BM;

    // A-load mapping: 256 rows x 16 cols; 4 float4 per thread (rows r, r+64, r+128, r+192)
    int ar  = tid >> 2;            // 0..63
    int ac4 = (tid & 3) * 4;       // 0,4,8,12
    // B-load mapping: 16 rows x 64 cols, 1 float4 per thread
    int br  = tid >> 4;            // 0..15
    int bc4 = (tid & 15) * 4;      // 0..60

    const float* Aptr = A + (size_t)(mBase + ar) * K + ac4;
    const float* Bptr = B + (size_t)br * N + nBase + bc4;

    float acc[16][4];
#pragma unroll
    for (int i = 0; i < 16; i++)
#pragma unroll
        for (int j = 0; j < 4; j++) acc[i][j] = 0.f;

    int ktiles = K / BK;

    // prologue: load first tile into registers
    float4 pa[4], pb;
#pragma unroll
    for (int i = 0; i < 4; i++)
        pa[i] = *(const float4*)(Aptr + (size_t)(64 * i) * K);
    pb = *(const float4*)(Bptr);

    for (int kt = 0; kt < ktiles; kt++) {
#pragma unroll
        for (int i = 0; i < 4; i++) {
            int row = ar + 64 * i;
            As[ac4 + 0][row] = pa[i].x;
            As[ac4 + 1][row] = pa[i].y;
            As[ac4 + 2][row] = pa[i].z;
            As[ac4 + 3][row] = pa[i].w;
        }
        *(float4*)&Bs[br][bc4] = pb;
        __syncthreads();

        // prefetch next tile while FMAs run
        if (kt + 1 < ktiles) {
            Aptr += BK;
            Bptr += (size_t)BK * N;
#pragma unroll
            for (int i = 0; i < 4; i++)
                pa[i] = *(const float4*)(Aptr + (size_t)(64 * i) * K);
            pb = *(const float4*)(Bptr);
        }

#pragma unroll
        for (int kk = 0; kk < BK; kk++) {
            float4 av0 = *(const float4*)&As[kk][ty * 16 + 0];
            float4 av1 = *(const float4*)&As[kk][ty * 16 + 4];
            float4 av2 = *(const float4*)&As[kk][ty * 16 + 8];
            float4 av3 = *(const float4*)&As[kk][ty * 16 + 12];
            float4 bv4 = *(const float4*)&Bs[kk][tx * 4];
            float a[16] = {av0.x, av0.y, av0.z, av0.w,
                           av1.x, av1.y, av1.z, av1.w,
                           av2.x, av2.y, av2.z, av2.w,
                           av3.x, av3.y, av3.z, av3.w};
            float b[4] = {bv4.x, bv4.y, bv4.z, bv4.w};
#pragma unroll
            for (int i = 0; i < 16; i++)
#pragma unroll
                for (int j = 0; j < 4; j++) acc[i][j] = fmaf(a[i], b[j], acc[i][j]);
        }
        __syncthreads();
    }

    // epilogue
    float bv[4];
    if (EPI & EPI_BIAS) {
#pragma unroll
        for (int j = 0; j < 4; j++) bv[j] = bias[nBase + tx * 4 + j];
    }
#pragma unroll
    for (int i = 0; i < 16; i++) {
        size_t row = (size_t)(mBase + ty * 16 + i);
        size_t off = row * N + nBase + tx * 4;
        float o[4];
#pragma unroll
        for (int j = 0; j < 4; j++) {
            float v = acc[i][j];
            if (EPI & EPI_BIAS) v += bv[j];
            if (EPI & EPI_GELU) v = gelu_exact(v);
            o[j] = v;
        }
        if (EPI & EPI_RESID) {
            float4 r = *(const float4*)(resid + off);
            o[0] += r.x; o[1] += r.y; o[2] += r.z; o[3] += r.w;
        }
        float4 out4;
        out4.x = o[0]; out4.y = o[1]; out4.z = o[2]; out4.w = o[3];
        *(float4*)(C + off) = out4;
    }
}

// ---------------- windowed attention: one block per (window, head) ----------------
__global__ __launch_bounds__(128)
void attn_kernel(const float* __restrict__ qkv,
                 const float* __restrict__ bias_table,
                 const int* __restrict__ rel_index,
                 float* __restrict__ out)
{
    __shared__ float qs[NTOK * HD];        // [t*32+d], pre-scaled
    __shared__ float ks[HD * 50];          // transposed [d*50+t]
    __shared__ float vs[NTOK * HD];        // [t*32+d]
    __shared__ float bsm[NTOK * NTOK];     // [i*49+j]
    __shared__ float sc[NTOK * 50];        // scores [i*50+j]

    int b = blockIdx.x;
    int h = blockIdx.y;
    int tid = threadIdx.x;
    const float scale = 0.17677669529663688110f; // 32^-0.5

    for (int idx = tid; idx < NTOK * HD; idx += 128) {
        int t = idx >> 5, d = idx & 31;
        size_t base = ((size_t)(b * NTOK + t)) * (3 * DIMC) + h * HD + d;
        qs[t * HD + d] = qkv[base] * scale;
        ks[d * 50 + t] = qkv[base + DIMC];
        vs[t * HD + d] = qkv[base + 2 * DIMC];
    }
    for (int idx = tid; idx < NTOK * NTOK; idx += 128) {
        bsm[idx] = bias_table[rel_index[idx] * HEADS + h];
    }
    __syncthreads();

    for (int idx = tid; idx < NTOK * NTOK; idx += 128) {
        int i = idx / NTOK, j = idx - i * NTOK;
        float s = 0.f;
#pragma unroll
        for (int d = 0; d < HD; d++) s = fmaf(qs[i * HD + d], ks[d * 50 + j], s);
        sc[i * 50 + j] = s + bsm[idx];
    }
    __syncthreads();

    if (tid < NTOK) {
        float mx = -1e30f;
#pragma unroll 7
        for (int j = 0; j < NTOK; j++) mx = fmaxf(mx, sc[tid * 50 + j]);
        float sum = 0.f;
#pragma unroll 7
        for (int j = 0; j < NTOK; j++) {
            float e = expf(sc[tid * 50 + j] - mx);
            sc[tid * 50 + j] = e;
            sum += e;
        }
        float inv = 1.f / sum;
#pragma unroll 7
        for (int j = 0; j < NTOK; j++) sc[tid * 50 + j] *= inv;
    }
    __syncthreads();

    for (int idx = tid; idx < NTOK * HD; idx += 128) {
        int t = idx >> 5, d = idx & 31;
        float s = 0.f;
#pragma unroll 7
        for (int j = 0; j < NTOK; j++) s = fmaf(sc[t * 50 + j], vs[j * HD + d], s);
        out[((size_t)(b * NTOK + t)) * DIMC + h * HD + d] = s;
    }
}

// ---------------- launch ----------------
extern "C" void kernel_launch(void* const* d_in, const int* in_sizes, int n_in,
                              void* d_out, int out_size)
{
    const float* x       = (const float*)d_in[0];
    const float* ln1_g   = (const float*)d_in[1];
    const float* ln1_b   = (const float*)d_in[2];
    const float* qkv_w   = (const float*)d_in[3];
    const float* proj_w  = (const float*)d_in[4];
    const float* proj_b  = (const float*)d_in[5];
    const float* btab    = (const float*)d_in[6];
    const float* ln2_g   = (const float*)d_in[7];
    const float* ln2_b   = (const float*)d_in[8];
    const float* fc1_w   = (const float*)d_in[9];
    const float* fc1_b   = (const float*)d_in[10];
    const float* fc2_w   = (const float*)d_in[11];
    const float* fc2_b   = (const float*)d_in[12];
    const int*   relidx  = (const int*)d_in[13];
    float* out = (float*)d_out;

    float *xln, *qkv, *att, *x2, *hid;
    cudaGetSymbolAddress((void**)&xln, g_xln);
    cudaGetSymbolAddress((void**)&qkv, g_qkv);
    cudaGetSymbolAddress((void**)&att, g_att);
    cudaGetSymbolAddress((void**)&x2,  g_x2);
    cudaGetSymbolAddress((void**)&hid, g_hid);

    // 1) LN1
    ln_kernel<<<ROWS / 8, 256>>>(x, ln1_g, ln1_b, xln);
    // 2) QKV gemm: (ROWS,192)x(192,576)
    gemm_kernel<0><<<dim3(3 * DIMC / BN, ROWS / BM), 256>>>(xln, qkv_w, nullptr, nullptr, qkv, ROWS, 3 * DIMC, DIMC);
    // 3) attention
    attn_kernel<<<dim3(BW, HEADS), 128>>>(qkv, btab, relidx, att);
    // 4) proj + bias + residual(x) -> x2
    gemm_kernel<EPI_BIAS | EPI_RESID><<<dim3(DIMC / BN, ROWS / BM), 256>>>(att, proj_w, proj_b, x, x2, ROWS, DIMC, DIMC);
    // 5) LN2 -> xln (reuse)
    ln_kernel<<<ROWS / 8, 256>>>(x2, ln2_g, ln2_b, xln);
    // 6) fc1 + bias + gelu
    gemm_kernel<EPI_BIAS | EPI_GELU><<<dim3(HIDDEN / BN, ROWS / BM), 256>>>(xln, fc1_w, fc1_b, nullptr, hid, ROWS, HIDDEN, DIMC);
    // 7) fc2 + bias + residual(x2) -> out
    gemm_kernel<EPI_BIAS | EPI_RESID><<<dim3(DIMC / BN, ROWS / BM), 256>>>(hid, fc2_w, fc2_b, x2, out, ROWS, DIMC, HIDDEN);
}

// round 10
// speedup vs baseline: 1.8684x; 1.5178x over previous
#include <cuda_runtime.h>
#include <cuda_bf16.h>
#include <math.h>
#include <stdint.h>

// ---------------- problem constants ----------------
#define DIMC   192
#define HEADS  6
#define HD     32
#define NTOK   49
#define BW     4096
#define HIDDEN 768
#define ROWS   (BW * NTOK)   // 200704

// ---------------- scratch (device globals) ----------------
__device__ __nv_bfloat16 g_xln_h[(size_t)ROWS * DIMC];
__device__ __nv_bfloat16 g_xln_l[(size_t)ROWS * DIMC];
__device__ float         g_qkv [(size_t)ROWS * 3 * DIMC];
__device__ __nv_bfloat16 g_att_h[(size_t)ROWS * DIMC];
__device__ __nv_bfloat16 g_att_l[(size_t)ROWS * DIMC];
__device__ float         g_x2  [(size_t)ROWS * DIMC];
__device__ __nv_bfloat16 g_hid_h[(size_t)ROWS * HIDDEN];
__device__ __nv_bfloat16 g_hid_l[(size_t)ROWS * HIDDEN];
// transposed weights [N][K], hi/lo
__device__ __nv_bfloat16 g_wqkv_h[576 * 192], g_wqkv_l[576 * 192];
__device__ __nv_bfloat16 g_wproj_h[192 * 192], g_wproj_l[192 * 192];
__device__ __nv_bfloat16 g_wfc1_h[768 * 192], g_wfc1_l[768 * 192];
__device__ __nv_bfloat16 g_wfc2_h[192 * 768], g_wfc2_l[192 * 768];

// ---------------- helpers ----------------
__device__ __forceinline__ uint32_t smem_u32(const void* p) {
    uint32_t a;
    asm("{ .reg .u64 t; cvta.to.shared.u64 t, %1; cvt.u32.u64 %0, t; }" : "=r"(a) : "l"(p));
    return a;
}
__device__ __forceinline__ uint32_t lds32(uint32_t a) {
    uint32_t v;
    asm volatile("ld.shared.b32 %0, [%1];" : "=r"(v) : "r"(a));
    return v;
}
#define CP16(sm, gp) asm volatile("cp.async.cg.shared.global [%0], [%1], 16;" :: "r"(sm), "l"(gp) : "memory")
#define CP_COMMIT()  asm volatile("cp.async.commit_group;" ::: "memory")
#define CP_WAIT1()   asm volatile("cp.async.wait_group 1;" ::: "memory")
#define CP_WAIT0()   asm volatile("cp.async.wait_group 0;" ::: "memory")
#define SWZ(x) ((x) ^ (((x) >> 3) & 0x70))

__device__ __forceinline__ void mma_bf16(float c[4],
    uint32_t a0, uint32_t a1, uint32_t a2, uint32_t a3, uint32_t b0, uint32_t b1)
{
    asm volatile(
        "mma.sync.aligned.m16n8k16.row.col.f32.bf16.bf16.f32 "
        "{%0,%1,%2,%3}, {%4,%5,%6,%7}, {%8,%9}, {%0,%1,%2,%3};"
        : "+f"(c[0]), "+f"(c[1]), "+f"(c[2]), "+f"(c[3])
        : "r"(a0), "r"(a1), "r"(a2), "r"(a3), "r"(b0), "r"(b1));
}

__device__ __forceinline__ void bf16split(float x, __nv_bfloat16& h, __nv_bfloat16& l)
{
    h = __float2bfloat16(x);
    l = __float2bfloat16(x - __bfloat162float(h));
}
__device__ __forceinline__ float gelu_exact(float v)
{
    return 0.5f * v * (1.f + erff(v * 0.70710678118654752440f));
}

// ---------------- weight convert + transpose: w[K][N] f32 -> hi/lo [N][K] bf16 ----------------
__global__ void wconv(const float* __restrict__ w, __nv_bfloat16* __restrict__ hi,
                      __nv_bfloat16* __restrict__ lo, int K, int N)
{
    int idx = blockIdx.x * 256 + threadIdx.x;
    if (idx >= K * N) return;
    int k = idx / N, n = idx - k * N;
    __nv_bfloat16 h, l;
    bf16split(w[idx], h, l);
    hi[(size_t)n * K + k] = h;
    lo[(size_t)n * K + k] = l;
}

// ---------------- LayerNorm -> hi/lo bf16 ----------------
__global__ void ln_kernel(const float* __restrict__ x,
                          const float* __restrict__ g,
                          const float* __restrict__ b,
                          __nv_bfloat16* __restrict__ yh,
                          __nv_bfloat16* __restrict__ yl)
{
    int warp = (blockIdx.x * blockDim.x + threadIdx.x) >> 5;
    int lane = threadIdx.x & 31;
    if (warp >= ROWS) return;
    const float* xr = x + (size_t)warp * DIMC;
    float v[6];
    float s = 0.f, sq = 0.f;
#pragma unroll
    for (int i = 0; i < 6; i++) {
        v[i] = xr[lane + 32 * i];
        s += v[i]; sq += v[i] * v[i];
    }
#pragma unroll
    for (int o = 16; o > 0; o >>= 1) {
        s  += __shfl_xor_sync(0xffffffffu, s,  o);
        sq += __shfl_xor_sync(0xffffffffu, sq, o);
    }
    float mu = s * (1.f / DIMC);
    float var = sq * (1.f / DIMC) - mu * mu;
    float rs = rsqrtf(var + 1e-5f);
#pragma unroll
    for (int i = 0; i < 6; i++) {
        int c = lane + 32 * i;
        float y = (v[i] - mu) * rs * g[c] + b[c];
        __nv_bfloat16 h, l;
        bf16split(y, h, l);
        yh[(size_t)warp * DIMC + c] = h;
        yl[(size_t)warp * DIMC + c] = l;
    }
}

// ---------------- tensor-core GEMM (mma.sync bf16 hi/lo split) ----------------
// C[M,N] = A[M,K] @ Bw[N,K]^T.  Block: 128(M) x 192(N), BK=64, 512 threads.
#define EPI_BIAS  1
#define EPI_RESID 2
#define EPI_GELU  4
#define EPI_SPLIT 8

#define SA_H 0
#define SA_L 16384
#define SB_H 32768
#define SB_L 57344
#define BUFSZ 81920
#define SMEM_G (2 * BUFSZ)   // 163840

template <int EPI>
__global__ void __launch_bounds__(512, 1)
tc_gemm(const __nv_bfloat16* __restrict__ Ah, const __nv_bfloat16* __restrict__ Al,
        const __nv_bfloat16* __restrict__ Bh, const __nv_bfloat16* __restrict__ Bl,
        const float* __restrict__ bias, const float* __restrict__ resid,
        float* __restrict__ Cf, __nv_bfloat16* __restrict__ Ch, __nv_bfloat16* __restrict__ Cl,
        int M, int N, int K)
{
    extern __shared__ char smem[];
    uint32_t sb = smem_u32(smem);
    int tid  = threadIdx.x;
    int wid  = tid >> 5, lane = tid & 31;
    int g    = lane >> 2, t = lane & 3;
    int wm   = wid & 3;          // 4 warps along M: rows wm*32
    int wn   = wid >> 2;         // 4 warps along N: cols wn*48
    int mBase = blockIdx.y * 128;
    int nBase = blockIdx.x * 192;

    // copy mapping
    int a_row = tid >> 2;            // 0..127
    int a_ch0 = (tid & 3) * 2;       // 16B chunks {0..7}, 2 per thread

    float acc[2][6][4];
#pragma unroll
    for (int i = 0; i < 2; i++)
#pragma unroll
        for (int j = 0; j < 6; j++)
#pragma unroll
            for (int k2 = 0; k2 < 4; k2++) acc[i][j][k2] = 0.f;

    int chunks = K / 64;

    auto issue_copy = [&](int ck) {
        uint32_t bo = sb + (uint32_t)(ck & 1) * BUFSZ;
        int kB = ck * 64;
        const __nv_bfloat16* gAh = Ah + (size_t)(mBase + a_row) * K + kB;
        const __nv_bfloat16* gAl = Al + (size_t)(mBase + a_row) * K + kB;
#pragma unroll
        for (int i = 0; i < 2; i++) {
            int ch = a_ch0 + i;
            uint32_t so = SWZ((uint32_t)(a_row * 128 + ch * 16));
            CP16(bo + SA_H + so, gAh + ch * 8);
            CP16(bo + SA_L + so, gAl + ch * 8);
        }
#pragma unroll
        for (int i = 0; i < 3; i++) {
            int idx = tid + 512 * i;          // < 1536 = 192 rows * 8 chunks
            int br = idx >> 3, bch = idx & 7;
            uint32_t so = SWZ((uint32_t)(br * 128 + bch * 16));
            const __nv_bfloat16* gBh = Bh + (size_t)(nBase + br) * K + kB + bch * 8;
            const __nv_bfloat16* gBl = Bl + (size_t)(nBase + br) * K + kB + bch * 8;
            CP16(bo + SB_H + so, gBh);
            CP16(bo + SB_L + so, gBl);
        }
        CP_COMMIT();
    };

    issue_copy(0);
    for (int ck = 0; ck < chunks; ck++) {
        if (ck + 1 < chunks) { issue_copy(ck + 1); CP_WAIT1(); }
        else                 { CP_WAIT0(); }
        __syncthreads();

        uint32_t bo = sb + (uint32_t)(ck & 1) * BUFSZ;
        uint32_t pAh = bo + SA_H, pAl = bo + SA_L;
        uint32_t pBh = bo + SB_H, pBl = bo + SB_L;

#pragma unroll
        for (int ks = 0; ks < 4; ks++) {
            uint32_t ah[2][4], al[2][4];
#pragma unroll
            for (int mt = 0; mt < 2; mt++) {
                int r0 = wm * 32 + mt * 16 + g;
                uint32_t o0 = SWZ((uint32_t)(r0 * 128 + ks * 32 + t * 4));
                uint32_t o1 = SWZ((uint32_t)((r0 + 8) * 128 + ks * 32 + t * 4));
                uint32_t o2 = SWZ((uint32_t)(r0 * 128 + ks * 32 + t * 4 + 16));
                uint32_t o3 = SWZ((uint32_t)((r0 + 8) * 128 + ks * 32 + t * 4 + 16));
                ah[mt][0] = lds32(pAh + o0); ah[mt][1] = lds32(pAh + o1);
                ah[mt][2] = lds32(pAh + o2); ah[mt][3] = lds32(pAh + o3);
                al[mt][0] = lds32(pAl + o0); al[mt][1] = lds32(pAl + o1);
                al[mt][2] = lds32(pAl + o2); al[mt][3] = lds32(pAl + o3);
            }
#pragma unroll
            for (int nt = 0; nt < 6; nt++) {
                int rn = wn * 48 + nt * 8 + g;
                uint32_t ob0 = SWZ((uint32_t)(rn * 128 + ks * 32 + t * 4));
                uint32_t ob1 = SWZ((uint32_t)(rn * 128 + ks * 32 + t * 4 + 16));
                uint32_t bh0 = lds32(pBh + ob0), bh1 = lds32(pBh + ob1);
                uint32_t bl0 = lds32(pBl + ob0), bl1 = lds32(pBl + ob1);
#pragma unroll
                for (int mt = 0; mt < 2; mt++) {
                    mma_bf16(acc[mt][nt], ah[mt][0], ah[mt][1], ah[mt][2], ah[mt][3], bh0, bh1);
                    mma_bf16(acc[mt][nt], ah[mt][0], ah[mt][1], ah[mt][2], ah[mt][3], bl0, bl1);
                    mma_bf16(acc[mt][nt], al[mt][0], al[mt][1], al[mt][2], al[mt][3], bh0, bh1);
                }
            }
        }
        __syncthreads();
    }

    // ---- epilogue ----
#pragma unroll
    for (int mt = 0; mt < 2; mt++) {
#pragma unroll
        for (int nt = 0; nt < 6; nt++) {
            int col = nBase + wn * 48 + nt * 8 + t * 2;
            float b0 = 0.f, b1 = 0.f;
            if (EPI & EPI_BIAS) { b0 = bias[col]; b1 = bias[col + 1]; }
#pragma unroll
            for (int h = 0; h < 2; h++) {
                size_t row = (size_t)(mBase + wm * 32 + mt * 16 + g + h * 8);
                size_t off = row * N + col;
                float v0 = acc[mt][nt][h * 2 + 0] + b0;
                float v1 = acc[mt][nt][h * 2 + 1] + b1;
                if (EPI & EPI_GELU) { v0 = gelu_exact(v0); v1 = gelu_exact(v1); }
                if (EPI & EPI_RESID) {
                    float2 r = *(const float2*)(resid + off);
                    v0 += r.x; v1 += r.y;
                }
                if (EPI & EPI_SPLIT) {
                    __nv_bfloat16 h0, l0, h1, l1;
                    bf16split(v0, h0, l0);
                    bf16split(v1, h1, l1);
                    __nv_bfloat162 hh, ll;
                    hh.x = h0; hh.y = h1;
                    ll.x = l0; ll.y = l1;
                    *(__nv_bfloat162*)(Ch + off) = hh;
                    *(__nv_bfloat162*)(Cl + off) = ll;
                } else {
                    float2 o; o.x = v0; o.y = v1;
                    *(float2*)(Cf + off) = o;
                }
            }
        }
    }
}

// ---------------- windowed attention ----------------
__global__ __launch_bounds__(128)
void attn_kernel(const float* __restrict__ qkv,
                 const float* __restrict__ bias_table,
                 const int* __restrict__ rel_index,
                 __nv_bfloat16* __restrict__ out_h,
                 __nv_bfloat16* __restrict__ out_l)
{
    __shared__ float qs[NTOK * HD];
    __shared__ float ks[HD * 50];
    __shared__ float vs[NTOK * HD];
    __shared__ float bsm[NTOK * NTOK];
    __shared__ float sc[NTOK * 50];

    int b = blockIdx.x;
    int h = blockIdx.y;
    int tid = threadIdx.x;
    const float scale = 0.17677669529663688110f;

    for (int idx = tid; idx < NTOK * HD; idx += 128) {
        int t = idx >> 5, d = idx & 31;
        size_t base = ((size_t)(b * NTOK + t)) * (3 * DIMC) + h * HD + d;
        qs[t * HD + d] = qkv[base] * scale;
        ks[d * 50 + t] = qkv[base + DIMC];
        vs[t * HD + d] = qkv[base + 2 * DIMC];
    }
    for (int idx = tid; idx < NTOK * NTOK; idx += 128)
        bsm[idx] = bias_table[rel_index[idx] * HEADS + h];
    __syncthreads();

    for (int idx = tid; idx < NTOK * NTOK; idx += 128) {
        int i = idx / NTOK, j = idx - i * NTOK;
        float s = 0.f;
#pragma unroll
        for (int d = 0; d < HD; d++) s = fmaf(qs[i * HD + d], ks[d * 50 + j], s);
        sc[i * 50 + j] = s + bsm[idx];
    }
    __syncthreads();

    if (tid < NTOK) {
        float mx = -1e30f;
#pragma unroll 7
        for (int j = 0; j < NTOK; j++) mx = fmaxf(mx, sc[tid * 50 + j]);
        float sum = 0.f;
#pragma unroll 7
        for (int j = 0; j < NTOK; j++) {
            float e = expf(sc[tid * 50 + j] - mx);
            sc[tid * 50 + j] = e;
            sum += e;
        }
        float inv = 1.f / sum;
#pragma unroll 7
        for (int j = 0; j < NTOK; j++) sc[tid * 50 + j] *= inv;
    }
    __syncthreads();

    for (int idx = tid; idx < NTOK * HD; idx += 128) {
        int t = idx >> 5, d = idx & 31;
        float s = 0.f;
#pragma unroll 7
        for (int j = 0; j < NTOK; j++) s = fmaf(sc[t * 50 + j], vs[j * HD + d], s);
        size_t off = ((size_t)(b * NTOK + t)) * DIMC + h * HD + d;
        __nv_bfloat16 hh, ll;
        bf16split(s, hh, ll);
        out_h[off] = hh;
        out_l[off] = ll;
    }
}

// ---------------- launch ----------------
extern "C" void kernel_launch(void* const* d_in, const int* in_sizes, int n_in,
                              void* d_out, int out_size)
{
    const float* x       = (const float*)d_in[0];
    const float* ln1_g   = (const float*)d_in[1];
    const float* ln1_b   = (const float*)d_in[2];
    const float* qkv_w   = (const float*)d_in[3];
    const float* proj_w  = (const float*)d_in[4];
    const float* proj_b  = (const float*)d_in[5];
    const float* btab    = (const float*)d_in[6];
    const float* ln2_g   = (const float*)d_in[7];
    const float* ln2_b   = (const float*)d_in[8];
    const float* fc1_w   = (const float*)d_in[9];
    const float* fc1_b   = (const float*)d_in[10];
    const float* fc2_w   = (const float*)d_in[11];
    const float* fc2_b   = (const float*)d_in[12];
    const int*   relidx  = (const int*)d_in[13];
    float* out = (float*)d_out;

    __nv_bfloat16 *xln_h, *xln_l, *att_h, *att_l, *hid_h, *hid_l;
    __nv_bfloat16 *wqkv_h, *wqkv_l, *wproj_h, *wproj_l, *wfc1_h, *wfc1_l, *wfc2_h, *wfc2_l;
    float *qkv, *x2;
    cudaGetSymbolAddress((void**)&xln_h, g_xln_h);
    cudaGetSymbolAddress((void**)&xln_l, g_xln_l);
    cudaGetSymbolAddress((void**)&qkv,   g_qkv);
    cudaGetSymbolAddress((void**)&att_h, g_att_h);
    cudaGetSymbolAddress((void**)&att_l, g_att_l);
    cudaGetSymbolAddress((void**)&x2,    g_x2);
    cudaGetSymbolAddress((void**)&hid_h, g_hid_h);
    cudaGetSymbolAddress((void**)&hid_l, g_hid_l);
    cudaGetSymbolAddress((void**)&wqkv_h, g_wqkv_h);
    cudaGetSymbolAddress((void**)&wqkv_l, g_wqkv_l);
    cudaGetSymbolAddress((void**)&wproj_h, g_wproj_h);
    cudaGetSymbolAddress((void**)&wproj_l, g_wproj_l);
    cudaGetSymbolAddress((void**)&wfc1_h, g_wfc1_h);
    cudaGetSymbolAddress((void**)&wfc1_l, g_wfc1_l);
    cudaGetSymbolAddress((void**)&wfc2_h, g_wfc2_h);
    cudaGetSymbolAddress((void**)&wfc2_l, g_wfc2_l);

    cudaFuncSetAttribute(tc_gemm<0>, cudaFuncAttributeMaxDynamicSharedMemorySize, SMEM_G);
    cudaFuncSetAttribute(tc_gemm<EPI_BIAS | EPI_RESID>, cudaFuncAttributeMaxDynamicSharedMemorySize, SMEM_G);
    cudaFuncSetAttribute(tc_gemm<EPI_BIAS | EPI_GELU | EPI_SPLIT>, cudaFuncAttributeMaxDynamicSharedMemorySize, SMEM_G);

    // 0) weight conversion (transpose + hi/lo split)
    wconv<<<(192 * 576 + 255) / 256, 256>>>(qkv_w,  wqkv_h,  wqkv_l,  192, 576);
    wconv<<<(192 * 192 + 255) / 256, 256>>>(proj_w, wproj_h, wproj_l, 192, 192);
    wconv<<<(192 * 768 + 255) / 256, 256>>>(fc1_w,  wfc1_h,  wfc1_l,  192, 768);
    wconv<<<(768 * 192 + 255) / 256, 256>>>(fc2_w,  wfc2_h,  wfc2_l,  768, 192);

    // 1) LN1 -> hi/lo
    ln_kernel<<<ROWS / 8, 256>>>(x, ln1_g, ln1_b, xln_h, xln_l);
    // 2) QKV: (ROWS,192) x (192,576) -> f32
    tc_gemm<0><<<dim3(576 / 192, ROWS / 128), 512, SMEM_G>>>(
        xln_h, xln_l, wqkv_h, wqkv_l, nullptr, nullptr, qkv, nullptr, nullptr, ROWS, 576, 192);
    // 3) attention -> hi/lo
    attn_kernel<<<dim3(BW, HEADS), 128>>>(qkv, btab, relidx, att_h, att_l);
    // 4) proj + bias + residual(x) -> x2 (f32)
    tc_gemm<EPI_BIAS | EPI_RESID><<<dim3(1, ROWS / 128), 512, SMEM_G>>>(
        att_h, att_l, wproj_h, wproj_l, proj_b, x, x2, nullptr, nullptr, ROWS, 192, 192);
    // 5) LN2 -> hi/lo
    ln_kernel<<<ROWS / 8, 256>>>(x2, ln2_g, ln2_b, xln_h, xln_l);
    // 6) fc1 + bias + gelu -> hid (hi/lo bf16)
    tc_gemm<EPI_BIAS | EPI_GELU | EPI_SPLIT><<<dim3(HIDDEN / 192, ROWS / 128), 512, SMEM_G>>>(
        xln_h, xln_l, wfc1_h, wfc1_l, fc1_b, nullptr, nullptr, hid_h, hid_l, ROWS, HIDDEN, 192);
    // 7) fc2 + bias + residual(x2) -> out (f32)
    tc_gemm<EPI_BIAS | EPI_RESID><<<dim3(1, ROWS / 128), 512, SMEM_G>>>(
        hid_h, hid_l, wfc2_h, wfc2_l, fc2_b, x2, out, nullptr, nullptr, ROWS, 192, HIDDEN);
}